// round 1
// baseline (speedup 1.0000x reference)
#include <cuda_runtime.h>

#define NV 8192          // variable nodes
#define RC 4096          // check nodes
#define DVD 3            // var degree
#define DCD 6            // check degree
#define EE (NV*DVD)      // 24576 edges
#define BB 1024          // batch
#define B4 (BB/4)        // 256 float4 columns
#define NITER 10

// Scratch (static __device__ allocations per harness rules)
__device__ float d_c2v[(size_t)EE*BB];   // check->var messages, [E][B], ~100 MB
__device__ float d_tot[(size_t)NV*BB];   // posterior totals,    [N][B], ~33 MB
__device__ float d_llr[(size_t)NV*BB];   // channel LLR^T,       [N][B], ~33 MB
__device__ int   d_cedge[RC*DCD];        // edges per check (sorted -> deterministic)
__device__ int   d_cnt[RC];

static __device__ __forceinline__ float fex2(float x){ float y; asm("ex2.approx.f32 %0,%1;":"=f"(y):"f"(x)); return y; }
static __device__ __forceinline__ float flg2(float x){ float y; asm("lg2.approx.f32 %0,%1;":"=f"(y):"f"(x)); return y; }

// llr_t[v][b] = 2 * received[b][v]   (tiled transpose, coalesced both sides)
__global__ void k_transpose(const float* __restrict__ rec){
    __shared__ float tile[32][33];
    int v0 = blockIdx.x*32, b0 = blockIdx.y*32;
    int tx = threadIdx.x, ty = threadIdx.y;          // 32 x 8
#pragma unroll
    for(int i=0;i<32;i+=8)
        tile[ty+i][tx] = rec[(size_t)(b0+ty+i)*NV + (v0+tx)];
    __syncthreads();
#pragma unroll
    for(int i=0;i<32;i+=8)
        d_llr[(size_t)(v0+ty+i)*BB + (b0+tx)] = 2.0f * tile[tx][ty+i];
}

__global__ void k_clear(){
    int i = blockIdx.x*blockDim.x + threadIdx.x;
    if(i < RC) d_cnt[i] = 0;
}

__global__ void k_build(const int* __restrict__ ec){
    int e = blockIdx.x*blockDim.x + threadIdx.x;
    if(e < EE){
        int c = ec[e];
        int s = atomicAdd(&d_cnt[c], 1);
        d_cedge[c*DCD + s] = e;
    }
}

// sort the 6 edge ids per check -> deterministic order regardless of atomics
__global__ void k_sort(){
    int c = blockIdx.x*blockDim.x + threadIdx.x;
    if(c >= RC) return;
    int v[DCD];
#pragma unroll
    for(int j=0;j<DCD;j++) v[j] = d_cedge[c*DCD+j];
#pragma unroll
    for(int i=0;i<DCD-1;i++)
#pragma unroll
        for(int j=0;j<DCD-1-i;j++)
            if(v[j] > v[j+1]){ int t=v[j]; v[j]=v[j+1]; v[j+1]=t; }
#pragma unroll
    for(int j=0;j<DCD;j++) d_cedge[c*DCD+j] = v[j];
}

// Check-node update. One block per check, 256 threads x float4 over the batch.
// v2c(e) = tot[var(e)] - c2v(e);  u = e^{-|v2c|};
// |loo_j| = prod_{k!=j}(1-u_k) / prod_{k!=j}(1+u_k)  (kept as A_j, B_j)
// c2v_j  = sign * clamp( ln((B_j+A_j)/(B_j-A_j)), <= 2*atanh(0.999) )
template<bool FIRST>
__global__ void __launch_bounds__(256) k_check(){
    int c = blockIdx.x, tid = threadIdx.x;
    const float4* __restrict__ tot4 = reinterpret_cast<const float4*>(FIRST ? d_llr : d_tot);
    float4* c2v4 = reinterpret_cast<float4*>(d_c2v);

    int e[DCD];
    float4 X[DCD];
#pragma unroll
    for(int j=0;j<DCD;j++){
        e[j] = d_cedge[c*DCD+j];
        int v = e[j]/3;
        float4 t = tot4[v*B4 + tid];
        if(!FIRST){
            float4 cc = c2v4[e[j]*B4 + tid];
            t.x-=cc.x; t.y-=cc.y; t.z-=cc.z; t.w-=cc.w;
        }
        X[j] = t;
    }

    float4 O[DCD];
#pragma unroll
    for(int l=0;l<4;l++){
        float a[DCD], b[DCD];
        unsigned sg[DCD], st = 0u;
#pragma unroll
        for(int j=0;j<DCD;j++){
            float x = (l==0)?X[j].x:(l==1)?X[j].y:(l==2)?X[j].z:X[j].w;
            unsigned s = __float_as_uint(x) & 0x80000000u;
            sg[j] = s; st ^= s;
            float u = fex2(fabsf(x) * -1.44269504f);   // e^{-|x|}
            a[j] = 1.0f - u;                            // |tanh| numerator
            b[j] = 1.0f + u;                            // denominator
        }
        float pa[DCD], pb[DCD];
        pa[0]=1.0f; pb[0]=1.0f;
#pragma unroll
        for(int j=1;j<DCD;j++){ pa[j]=pa[j-1]*a[j-1]; pb[j]=pb[j-1]*b[j-1]; }
        float sa=1.0f, sb=1.0f;
#pragma unroll
        for(int j=DCD-1;j>=0;j--){
            float A  = pa[j]*sa;
            float Bp = pb[j]*sb;
            sa *= a[j]; sb *= b[j];
            float mag = 0.69314718f * (flg2(Bp + A) - flg2(Bp - A));
            mag = fminf(mag, 7.6004148f);               // = 2*atanh(0.999f)
            float val = __uint_as_float(__float_as_uint(mag) | (st ^ sg[j]));
            if(l==0)O[j].x=val; else if(l==1)O[j].y=val; else if(l==2)O[j].z=val; else O[j].w=val;
        }
    }
#pragma unroll
    for(int j=0;j<DCD;j++) c2v4[e[j]*B4 + tid] = O[j];
}

// Variable-node totals: tot[v][b] = llr[v][b] + sum of the 3 incident c2v rows
__global__ void k_var(){
    int idx = blockIdx.x*blockDim.x + threadIdx.x;    // over NV*B4
    int v = idx >> 8, col = idx & 255;
    const float4* __restrict__ c4 = reinterpret_cast<const float4*>(d_c2v);
    const float4* __restrict__ l4 = reinterpret_cast<const float4*>(d_llr);
    float4* t4 = reinterpret_cast<float4*>(d_tot);
    int base = v*(3*B4) + col;
    float4 s  = l4[idx];
    float4 c0 = c4[base], c1 = c4[base+B4], c2 = c4[base+2*B4];
    s.x += c0.x + c1.x + c2.x;
    s.y += c0.y + c1.y + c2.y;
    s.z += c0.z + c1.z + c2.z;
    s.w += c0.w + c1.w + c2.w;
    t4[idx] = s;
}

// Final: out[b][v] = llr + sum c2v (transposed write), plus decoded bits if requested
__global__ void k_final(float* __restrict__ out, int do_bits){
    __shared__ float tile[32][33];
    int v0 = blockIdx.x*32, b0 = blockIdx.y*32;
    int tx = threadIdx.x, ty = threadIdx.y;           // 32 x 8
#pragma unroll
    for(int i=0;i<32;i+=8){
        int v = v0+ty+i, b = b0+tx;
        float f = d_llr[(size_t)v*BB+b]
                + d_c2v[(size_t)(3*v  )*BB+b]
                + d_c2v[(size_t)(3*v+1)*BB+b]
                + d_c2v[(size_t)(3*v+2)*BB+b];
        tile[ty+i][tx] = f;
    }
    __syncthreads();
#pragma unroll
    for(int i=0;i<32;i+=8){
        int b = b0+ty+i, v = v0+tx;
        float f = tile[tx][ty+i];
        out[(size_t)b*NV + v] = f;
        if(do_bits)
            out[(size_t)BB*NV + (size_t)b*NV + v] = (f < 0.0f) ? 1.0f : 0.0f;
    }
}

extern "C" void kernel_launch(void* const* d_in, const int* in_sizes, int n_in,
                              void* d_out, int out_size){
    const float* rec = (const float*)d_in[0];
    const int*   ec  = (const int*)d_in[2];   // edge_check (edge_var is repeat(arange(N),3))

    k_transpose<<<dim3(NV/32, BB/32), dim3(32,8)>>>(rec);
    k_clear<<<RC/256, 256>>>();
    k_build<<<EE/256, 256>>>(ec);
    k_sort<<<RC/256, 256>>>();

    k_check<true><<<RC, 256>>>();                       // iteration 1 (c2v == 0)
    for(int it=1; it<NITER; ++it){
        k_var<<<(NV*B4)/256, 256>>>();
        k_check<false><<<RC, 256>>>();
    }
    int do_bits = (out_size >= 2*NV*BB);
    k_final<<<dim3(NV/32, BB/32), dim3(32,8)>>>((float*)d_out, do_bits);
}